// round 13
// baseline (speedup 1.0000x reference)
#include <cuda_runtime.h>
#include <cuda_fp16.h>
#include <stdint.h>

#define N_NODES 50000
#define HALF_NODES 25000
#define N_EDGES 625000
#define IN_DIMS 128

#define GRID 148
#define THREADS 1024
#define WARPS 32
#define TOTAL_WARPS (GRID * WARPS)                                // 4736
#define RPW_H ((HALF_NODES + TOTAL_WARPS - 1) / TOTAL_WARPS)      // 6 rows/warp/half

// Per-CTA edge chunk, rounded UP TO EVEN (odd chunk -> misaligned int2, R11 trap).
#define EDGE_CHUNK_RAW ((N_EDGES + GRID - 1) / GRID)              // 4223
#define EDGE_CHUNK ((EDGE_CHUNK_RAW + 1) & ~1)                    // 4224
#define EDGE_ITERS ((EDGE_CHUNK + THREADS * 2 - 1) / (THREADS * 2))  // 3
#define TABLE_BYTES (N_NODES * 4)                                 // 200000
#define HALF_TABLE (HALF_NODES * 4)                               // 100000 (16B mult)

// Interleaved per-node table: {s = x.W_src + b, t = x.W_dst} as fp16.
__device__ __align__(16) __half2 g_st[N_NODES];
// Grid barrier counter: monotonic epochs across graph replays (2 rounds/replay).
__device__ unsigned g_bar = 0;

// ---- node rows: 8 lanes per row, 4 rows per warp-step, 6 shfls / 4 rows ----
__device__ __forceinline__ void compute_rows(const float* __restrict__ x,
                                             const float* __restrict__ W,
                                             float bias, int rs, int re,
                                             int lane) {
    int g = lane >> 3;          // which of 4 rows this lane serves
    int q = lane & 7;           // position within row (float4 granularity)
    for (int rb = rs; rb < re; rb += 4) {
        int row = rb + g;
        bool valid = row < re;
        const float4* xr = reinterpret_cast<const float4*>(x) + (size_t)row * (IN_DIMS / 4);
        float ps = 0.f, pt = 0.f;
        #pragma unroll
        for (int k = 0; k < 4; k++) {
            float4 xv = valid ? xr[q + 8 * k] : make_float4(0.f, 0.f, 0.f, 0.f);
            float4 ws = reinterpret_cast<const float4*>(W)[q + 8 * k];            // L1-hot
            float4 wd = reinterpret_cast<const float4*>(W + IN_DIMS)[q + 8 * k];  // L1-hot
            ps = fmaf(xv.x, ws.x, fmaf(xv.y, ws.y, fmaf(xv.z, ws.z, fmaf(xv.w, ws.w, ps))));
            pt = fmaf(xv.x, wd.x, fmaf(xv.y, wd.y, fmaf(xv.z, wd.z, fmaf(xv.w, wd.w, pt))));
        }
        // Reduce within the 8-lane group (xor of low 3 bits stays in-group).
        #pragma unroll
        for (int o = 4; o > 0; o >>= 1) {
            ps += __shfl_xor_sync(0xffffffffu, ps, o);
            pt += __shfl_xor_sync(0xffffffffu, pt, o);
        }
        // Lane 9g (q==g) of each group writes its row.
        if (q == g && valid)
            g_st[row] = make_half2(__float2half_rn(ps + bias), __float2half_rn(pt));
    }
}

__device__ __forceinline__ void grid_barrier(int tid) {
    __threadfence();
    __syncthreads();
    if (tid == 0) {
        unsigned old = atomicAdd(&g_bar, 1u);
        unsigned target = (old / GRID + 1u) * GRID;
        while (atomicAdd(&g_bar, 0u) < target) { }
    }
    __syncthreads();
}

__global__ void __launch_bounds__(THREADS, 1)
fused_kernel(const float* __restrict__ x,
             const int* __restrict__ ei,
             const float* __restrict__ W,
             const float* __restrict__ b,
             float* __restrict__ out) {
    extern __shared__ __half2 st[];
    __shared__ __align__(8) uint64_t mb[2];
    int tid  = threadIdx.x;
    int lane = tid & 31;
    int gw   = (int)blockIdx.x * WARPS + (tid >> 5);

    uint32_t s_base, mb0_a, mb1_a;
    asm("{ .reg .u64 t; cvta.to.shared.u64 t, %1; cvt.u32.u64 %0, t; }" : "=r"(s_base) : "l"(st));
    asm("{ .reg .u64 t; cvta.to.shared.u64 t, %1; cvt.u32.u64 %0, t; }" : "=r"(mb0_a) : "l"(&mb[0]));
    asm("{ .reg .u64 t; cvta.to.shared.u64 t, %1; cvt.u32.u64 %0, t; }" : "=r"(mb1_a) : "l"(&mb[1]));

    if (tid == 0) {
        asm volatile("mbarrier.init.shared.b64 [%0], 1;" :: "r"(mb0_a) : "memory");
        asm volatile("mbarrier.init.shared.b64 [%0], 1;" :: "r"(mb1_a) : "memory");
    }
    // (ordering to first use is provided by the grid barriers' __syncthreads)

    // ---- Phase 0: L2-prefetch this CTA's edge-index slice (no registers held) ----
    int ebase = (int)blockIdx.x * EDGE_CHUNK;
    int eend  = min(ebase + EDGE_CHUNK, N_EDGES);
    for (int off = tid * 32; off < EDGE_CHUNK; off += THREADS * 32) {
        asm volatile("prefetch.global.L2 [%0];" :: "l"(ei + ebase + off));
        asm volatile("prefetch.global.L2 [%0];" :: "l"(ei + N_EDGES + ebase + off));
    }

    float bias = __ldg(b);

    // ---- Phase 1a: lower-half node rows ----
    {
        int rs = gw * RPW_H;
        int re = min(rs + RPW_H, HALF_NODES);
        compute_rows(x, W, bias, rs, re, lane);
    }
    grid_barrier(tid);
    // Kick TMA bulk fill of H0 table -> smem (runs under H1 compute).
    if (tid == 0) {
        asm volatile("fence.proxy.async;" ::: "memory");
        asm volatile("mbarrier.arrive.expect_tx.shared.b64 _, [%0], %1;"
                     :: "r"(mb0_a), "r"((uint32_t)HALF_TABLE) : "memory");
        asm volatile("cp.async.bulk.shared::cluster.global.mbarrier::complete_tx::bytes"
                     " [%0], [%1], %2, [%3];"
                     :: "r"(s_base), "l"((const char*)g_st),
                        "r"((uint32_t)HALF_TABLE), "r"(mb0_a) : "memory");
    }

    // ---- Phase 1b: upper-half node rows (overlaps H0 fill) ----
    {
        int rs = HALF_NODES + gw * RPW_H;
        int re = min(rs + RPW_H, N_NODES);
        compute_rows(x, W, bias, rs, re, lane);
    }
    grid_barrier(tid);
    if (tid == 0) {
        asm volatile("fence.proxy.async;" ::: "memory");
        asm volatile("mbarrier.arrive.expect_tx.shared.b64 _, [%0], %1;"
                     :: "r"(mb1_a), "r"((uint32_t)HALF_TABLE) : "memory");
        asm volatile("cp.async.bulk.shared::cluster.global.mbarrier::complete_tx::bytes"
                     " [%0], [%1], %2, [%3];"
                     :: "r"(s_base + HALF_TABLE), "l"((const char*)g_st + HALF_TABLE),
                        "r"((uint32_t)HALF_TABLE), "r"(mb1_a) : "memory");
    }

    // ---- Load edge indices (L2-hot from prefetch) while fills complete ----
    int2 si[EDGE_ITERS], di[EDGE_ITERS];
    #pragma unroll
    for (int i = 0; i < EDGE_ITERS; i++) {
        int e = ebase + (i * THREADS + tid) * 2;
        if (e < eend) {
            si[i] = *reinterpret_cast<const int2*>(ei + e);
            di[i] = *reinterpret_cast<const int2*>(ei + N_EDGES + e);
        } else {
            si[i] = make_int2(0, 0);
            di[i] = make_int2(0, 0);
        }
    }

    // ---- Wait for both table halves ----
    #pragma unroll
    for (int m = 0; m < 2; m++) {
        uint32_t mba = m ? mb1_a : mb0_a;
        uint32_t done;
        asm volatile("{\n\t.reg .pred p;\n\t"
                     "mbarrier.try_wait.parity.shared.b64 p, [%1], %2;\n\t"
                     "selp.b32 %0, 1, 0, p;\n\t}"
                     : "=r"(done) : "r"(mba), "r"(0u) : "memory");
        if (!done) {
            asm volatile("{\n\t.reg .pred P1;\n\t"
                         "WL_%=:\n\t"
                         "mbarrier.try_wait.parity.shared.b64 P1, [%0], %1, 0x989680;\n\t"
                         "@P1 bra.uni WD_%=;\n\t"
                         "bra.uni WL_%=;\n\t"
                         "WD_%=:\n\t}"
                         :: "r"(mba), "r"(0u) : "memory");
        }
    }
    __syncthreads();

    // ---- Phase 3: smem gather, compute, store ----
    #pragma unroll
    for (int i = 0; i < EDGE_ITERS; i++) {
        int e = ebase + (i * THREADS + tid) * 2;
        if (e < eend) {
            __half2 a0 = st[si[i].x];
            __half2 c0 = st[di[i].x];
            __half2 a1 = st[si[i].y];
            __half2 c1 = st[di[i].y];
            float2 r;
            r.x = __low2float(a0) + __high2float(c0);
            r.y = __low2float(a1) + __high2float(c1);
            *reinterpret_cast<float2*>(out + e) = r;
        }
    }
}

extern "C" void kernel_launch(void* const* d_in, const int* in_sizes, int n_in,
                              void* d_out, int out_size) {
    const float* x   = (const float*)d_in[0];   // [N_NODES, 128] f32
    const int*   ei  = (const int*)d_in[1];     // [2, N_EDGES] int32
    const float* W   = (const float*)d_in[2];   // [1, 256] f32
    const float* b   = (const float*)d_in[3];   // [1] f32
    float*       out = (float*)d_out;           // [N_EDGES] f32

    cudaFuncSetAttribute(fused_kernel,
                         cudaFuncAttributeMaxDynamicSharedMemorySize, TABLE_BYTES);
    fused_kernel<<<GRID, THREADS, TABLE_BYTES>>>(x, ei, W, b, out);
}

// round 14
// speedup vs baseline: 1.2260x; 1.2260x over previous
#include <cuda_runtime.h>
#include <cuda_fp16.h>
#include <stdint.h>

#define N_NODES 50000
#define N_EDGES 625000
#define IN_DIMS 128

#define GRID 148
#define THREADS 1024
#define WARPS 32
#define TOTAL_WARPS (GRID * WARPS)                                // 4736
#define ROWS_PER_WARP ((N_NODES + TOTAL_WARPS - 1) / TOTAL_WARPS) // 11

// Per-CTA edge chunk, rounded UP TO EVEN (odd chunk -> misaligned int2 trap).
#define EDGE_CHUNK_RAW ((N_EDGES + GRID - 1) / GRID)              // 4223
#define EDGE_CHUNK ((EDGE_CHUNK_RAW + 1) & ~1)                    // 4224
#define EDGE_ITERS ((EDGE_CHUNK + THREADS * 2 - 1) / (THREADS * 2))  // 3
#define TABLE_BYTES (N_NODES * 4)                                 // 200000

// Interleaved per-node table: {s = x.W_src + b, t = x.W_dst} as fp16.
__device__ __align__(16) __half2 g_st[N_NODES];
// Grid barrier counter: monotonic epochs across graph replays.
__device__ unsigned g_bar = 0;

__device__ __forceinline__ float dot4(float4 a, float4 w, float acc) {
    return fmaf(a.x, w.x, fmaf(a.y, w.y, fmaf(a.z, w.z, fmaf(a.w, w.w, acc))));
}

__global__ void __launch_bounds__(THREADS, 1)
fused_kernel(const float* __restrict__ x,
             const int* __restrict__ ei,
             const float* __restrict__ W,
             const float* __restrict__ b,
             float* __restrict__ out) {
    extern __shared__ __half2 st[];
    int tid  = threadIdx.x;
    int lane = tid & 31;
    int gw   = (int)blockIdx.x * WARPS + (tid >> 5);

    // ---- Phase 0: L2-prefetch this CTA's edge-index slice (no registers held) ----
    int ebase = (int)blockIdx.x * EDGE_CHUNK;     // even -> int2/float2 aligned
    int eend  = min(ebase + EDGE_CHUNK, N_EDGES);
    for (int off = tid * 32; off < EDGE_CHUNK; off += THREADS * 32) {
        asm volatile("prefetch.global.L2 [%0];" :: "l"(ei + ebase + off));
        asm volatile("prefetch.global.L2 [%0];" :: "l"(ei + N_EDGES + ebase + off));
    }

    // ---- Phase 1: node slice — 16 lanes per row, 2 rows per warp-step ----
    {
        int g = lane >> 4;            // 0..1 : which row of the pair
        int q = lane & 15;            // 0..15: float4 slot within row half
        // W slice held in registers (loaded once; W is 64 float4: src 0..31, dst 32..63)
        const float4* W4 = reinterpret_cast<const float4*>(W);
        const float4 ws0 = W4[q];
        const float4 ws1 = W4[q + 16];
        const float4 wd0 = W4[q + 32];
        const float4 wd1 = W4[q + 48];
        float bias = __ldg(b);

        int rs = gw * ROWS_PER_WARP;
        int re = min(rs + ROWS_PER_WARP, N_NODES);
        for (int rb = rs; rb < re; rb += 2) {
            int row = rb + g;
            bool valid = row < re;
            const float4* xr = reinterpret_cast<const float4*>(x) + (size_t)row * (IN_DIMS / 4);
            float4 a0 = valid ? xr[q]      : make_float4(0.f, 0.f, 0.f, 0.f);
            float4 a1 = valid ? xr[q + 16] : make_float4(0.f, 0.f, 0.f, 0.f);
            float ps = dot4(a1, ws1, dot4(a0, ws0, 0.f));
            float pt = dot4(a1, wd1, dot4(a0, wd0, 0.f));
            // Reduce across the 16-lane group (xor of low 4 bits stays in-group).
            #pragma unroll
            for (int o = 8; o > 0; o >>= 1) {
                ps += __shfl_xor_sync(0xffffffffu, ps, o);
                pt += __shfl_xor_sync(0xffffffffu, pt, o);
            }
            if (q == 0 && valid)
                g_st[row] = make_half2(__float2half_rn(ps + bias), __float2half_rn(pt));
        }
    }

    // ---- Grid barrier (monotonic epoch; all 148 CTAs are resident) ----
    __threadfence();
    __syncthreads();
    if (tid == 0) {
        unsigned old = atomicAdd(&g_bar, 1u);
        unsigned target = (old / GRID + 1u) * GRID;
        while (atomicAdd(&g_bar, 0u) < target) { }
    }
    __syncthreads();

    // ---- Phase 2: kick smem table fill (cp.async), then load indices (L2-hot) ----
    uint32_t s_base;
    asm("{ .reg .u64 t; cvta.to.shared.u64 t, %1; cvt.u32.u64 %0, t; }"
        : "=r"(s_base) : "l"(st));
    {
        const char* g_base = reinterpret_cast<const char*>(g_st);
        const int n_chunks = TABLE_BYTES / 16;   // 12500
        #pragma unroll 4
        for (int c = tid; c < n_chunks; c += THREADS) {
            asm volatile("cp.async.cg.shared.global [%0], [%1], 16;"
                         :: "r"(s_base + c * 16), "l"(g_base + (size_t)c * 16));
        }
        asm volatile("cp.async.commit_group;");
    }

    int2 si[EDGE_ITERS], di[EDGE_ITERS];
    #pragma unroll
    for (int i = 0; i < EDGE_ITERS; i++) {
        int e = ebase + (i * THREADS + tid) * 2;
        if (e < eend) {
            si[i] = *reinterpret_cast<const int2*>(ei + e);
            di[i] = *reinterpret_cast<const int2*>(ei + N_EDGES + e);
        } else {
            si[i] = make_int2(0, 0);
            di[i] = make_int2(0, 0);
        }
    }

    asm volatile("cp.async.wait_group 0;" ::: "memory");
    __syncthreads();

    // ---- Phase 3: smem gather, compute, store (bias folded in table) ----
    #pragma unroll
    for (int i = 0; i < EDGE_ITERS; i++) {
        int e = ebase + (i * THREADS + tid) * 2;
        if (e < eend) {
            __half2 a0 = st[si[i].x];
            __half2 c0 = st[di[i].x];
            __half2 a1 = st[si[i].y];
            __half2 c1 = st[di[i].y];
            float2 r;
            r.x = __low2float(a0) + __high2float(c0);
            r.y = __low2float(a1) + __high2float(c1);
            *reinterpret_cast<float2*>(out + e) = r;
        }
    }
}

extern "C" void kernel_launch(void* const* d_in, const int* in_sizes, int n_in,
                              void* d_out, int out_size) {
    const float* x   = (const float*)d_in[0];   // [N_NODES, 128] f32
    const int*   ei  = (const int*)d_in[1];     // [2, N_EDGES] int32
    const float* W   = (const float*)d_in[2];   // [1, 256] f32
    const float* b   = (const float*)d_in[3];   // [1] f32
    float*       out = (float*)d_out;           // [N_EDGES] f32

    cudaFuncSetAttribute(fused_kernel,
                         cudaFuncAttributeMaxDynamicSharedMemorySize, TABLE_BYTES);
    fused_kernel<<<GRID, THREADS, TABLE_BYTES>>>(x, ei, W, b, out);
}